// round 11
// baseline (speedup 1.0000x reference)
#include <cuda_runtime.h>

// RGCN constants
constexpr int N_   = 50000;
constexpr int E_   = 500000;
constexpr int R_   = 20;
constexpr int RT_  = 41;            // 2R+1
constexpr int B_   = 40;
constexpr int EMB_ = 16;
constexpr int C_   = 16;
constexpr int NE_  = N_ * EMB_;     // 800000
constexpr int RC_  = RT_ * C_;      // 656
constexpr int JP_  = NE_ / 2;       // 400000 j-pairs
constexpr int WBn  = JP_ / 128;     // 3125 w1 blocks (256 thr, lane-pairs)
constexpr int CBn  = (E_ + 255) / 256;   // count blocks
constexpr int NCOL1 = 21 * 16;      // group-1 row width (336) = max

// Scratch (static device globals)
__device__ float g_w1[(size_t)RT_ * NE_];   // [41][50000][16]  131 MB
__device__ float g_h[NE_];                  // layer-1 pre-activations
__device__ int   g_cnt[RT_ * N_];           // per-(r,s) edge counts
__device__ float g_w2f[EMB_ * RC_];         // w2 flat [e][r*16+c]
__device__ float g_mg[(size_t)N_ * NCOL1];  // per-GROUP m buffer, 67.2 MB (L2-resident)

// ---------------------------------------------------------------------------
// pre-pass: zero cnt & h, seed out with bias2, compute w2f. One launch.
__global__ void k_pre(float* __restrict__ out, const float* __restrict__ bias2,
                      const float* __restrict__ comps2,
                      const float* __restrict__ bases2) {
    int i = blockIdx.x * blockDim.x + threadIdx.x;
    if (i < RT_ * N_) g_cnt[i] = 0;
    if (i < NE_) { g_h[i] = 0.0f; out[i] = bias2[i & 15]; }
    if (i < RT_ * EMB_ * C_) {
        int r = i >> 8, ec = i & 255;
        int e = ec >> 4, c = ec & 15;
        float acc = 0.0f;
#pragma unroll
        for (int b = 0; b < B_; b++)
            acc = fmaf(comps2[r * B_ + b], bases2[b * 256 + ec], acc);
        g_w2f[e * RC_ + r * 16 + c] = acc;
    }
}

// ---------------------------------------------------------------------------
// Fused w1-GEMM + edge counting. Lane-pair b-split, f32x2, quad-packed comps.
__global__ void __launch_bounds__(256) k_w1c(const float* __restrict__ comps1,
                                             const float* __restrict__ bases1,
                                             const int* __restrict__ src,
                                             const int* __restrict__ dst,
                                             const int* __restrict__ rel) {
    if (blockIdx.x >= WBn) {
        int i = (blockIdx.x - WBn) * 256 + threadIdx.x;
        if (i < E_) {
            int r = rel[i];
            atomicAdd(&g_cnt[r * N_ + src[i]], 1);
            atomicAdd(&g_cnt[(r + R_) * N_ + dst[i]], 1);
        }
        return;
    }

    __shared__ __align__(16) ulonglong2 cs4[RT_ * 20];
    for (int t = threadIdx.x; t < RT_ * 20; t += 256) {
        int r = t / 20, k = t % 20;
        unsigned int ca = __float_as_uint(comps1[r * B_ + 2 * k]);
        unsigned int cb = __float_as_uint(comps1[r * B_ + 2 * k + 1]);
        ulonglong2 q;
        asm("mov.b64 %0, {%1, %1};" : "=l"(q.x) : "r"(ca));
        asm("mov.b64 %0, {%1, %1};" : "=l"(q.y) : "r"(cb));
        cs4[t] = q;
    }
    __syncthreads();

    int half = threadIdx.x & 1;
    int jp   = blockIdx.x * 128 + (threadIdx.x >> 1);

    unsigned long long bp[20];                      // 20 x float2 = 40 regs
#pragma unroll
    for (int k = 0; k < 20; k++)
        bp[k] = *(const unsigned long long*)
                 &bases1[(size_t)(half * 20 + k) * NE_ + 2 * jp];

    int kbase = half * 10;
#pragma unroll 1
    for (int r = 0; r < RT_; r++) {
        const ulonglong2* cq = &cs4[r * 20 + kbase];
        unsigned long long acc = 0ull;
#pragma unroll
        for (int k = 0; k < 10; k++) {
            ulonglong2 q = cq[k];
            asm("fma.rn.f32x2 %0, %1, %2, %0;" : "+l"(acc) : "l"(bp[2*k]),   "l"(q.x));
            asm("fma.rn.f32x2 %0, %1, %2, %0;" : "+l"(acc) : "l"(bp[2*k+1]), "l"(q.y));
        }
        unsigned long long other = __shfl_xor_sync(0xffffffffu, acc, 1);
        asm("add.rn.f32x2 %0, %0, %1;" : "+l"(acc) : "l"(other));
        if (!half)
            *(unsigned long long*)&g_w1[(size_t)r * NE_ + 2 * jp] = acc;
    }
}

// ---------------------------------------------------------------------------
// layer-1 scatter: h[s,:] += v * w1[r, o, :].  4 threads/edge, one RED.v4 each.
__global__ void k_l1(const int* __restrict__ src, const int* __restrict__ dst,
                     const int* __restrict__ rel) {
    int idx = blockIdx.x * blockDim.x + threadIdx.x;
    if (idx >= 2 * E_ * 4) return;
    int q  = idx & 3;
    int e2 = idx >> 2;
    int s, o, r;
    if (e2 < E_) { s = src[e2]; o = dst[e2]; r = rel[e2]; }
    else         { int e = e2 - E_; s = dst[e]; o = src[e]; r = rel[e] + R_; }
    float v = 1.0f / (float)g_cnt[r * N_ + s];
    const float4 w = *(const float4*)&g_w1[(size_t)r * NE_ + o * EMB_ + q * 4];
    float* hp = &g_h[s * EMB_ + q * 4];
    asm volatile("red.global.add.v4.f32 [%0], {%1, %2, %3, %4};"
                 :: "l"(hp), "f"(v * w.x), "f"(v * w.y), "f"(v * w.z), "f"(v * w.w)
                 : "memory");
}

// ---------------------------------------------------------------------------
// Per-group m GEMM: g_mg[o][rr][c] = sum_e relu1(h[o,e]) * w2f[e][(BASE+rr)*16+c]
// for rr in [0, NREL). f32x2 throughout; ILP-2 nodes; w2 slice in registers.
template<int BASE, int NREL>
__global__ void __launch_bounds__(128) k_mgemm_g(const float* __restrict__ bias1) {
    constexpr int NCOL = NREL * 16;
    constexpr int CHg  = NCOL / 4;
    int w    = threadIdx.x >> 5;
    int lane = threadIdx.x & 31;
    int le   = lane & 15;
    int chunk = w * 32 + lane;
    bool act = chunk < CHg;
    int ch = act ? chunk : 0;

    ulonglong2 w2r[EMB_];                 // packed {w0,w1},{w2,w3} per e: 64 regs
#pragma unroll
    for (int e = 0; e < EMB_; e++)
        w2r[e] = *(const ulonglong2*)&g_w2f[e * RC_ + BASE * 16 + ch * 4];
    float breg = bias1[le];
    const float* w1sl = &g_w1[(size_t)(RT_ - 1) * NE_];

    const int G = gridDim.x;
    int node = blockIdx.x;
    float h0 = 0.0f, h1 = 0.0f;
    if (node < N_)
        h0 = fmaxf(g_h[node * EMB_ + le] + w1sl[node * EMB_ + le] + breg, 0.0f);
    if (node + G < N_)
        h1 = fmaxf(g_h[(node + G) * EMB_ + le] + w1sl[(node + G) * EMB_ + le] + breg, 0.0f);

    for (; node < N_; node += 2 * G) {
        int n2 = node + 2 * G, n3 = node + 3 * G;
        float p0 = 0.0f, p1 = 0.0f;
        if (n2 < N_)
            p0 = fmaxf(g_h[n2 * EMB_ + le] + w1sl[n2 * EMB_ + le] + breg, 0.0f);
        if (n3 < N_)
            p1 = fmaxf(g_h[n3 * EMB_ + le] + w1sl[n3 * EMB_ + le] + breg, 0.0f);

        unsigned long long a0x = 0ull, a0y = 0ull, a1x = 0ull, a1y = 0ull;
#pragma unroll
        for (int e = 0; e < EMB_; e++) {
            float he0 = __shfl_sync(0xffffffffu, h0, e);
            float he1 = __shfl_sync(0xffffffffu, h1, e);
            unsigned long long d0, d1;
            asm("mov.b64 %0, {%1, %1};" : "=l"(d0) : "r"(__float_as_uint(he0)));
            asm("mov.b64 %0, {%1, %1};" : "=l"(d1) : "r"(__float_as_uint(he1)));
            asm("fma.rn.f32x2 %0, %1, %2, %0;" : "+l"(a0x) : "l"(d0), "l"(w2r[e].x));
            asm("fma.rn.f32x2 %0, %1, %2, %0;" : "+l"(a0y) : "l"(d0), "l"(w2r[e].y));
            asm("fma.rn.f32x2 %0, %1, %2, %0;" : "+l"(a1x) : "l"(d1), "l"(w2r[e].x));
            asm("fma.rn.f32x2 %0, %1, %2, %0;" : "+l"(a1y) : "l"(d1), "l"(w2r[e].y));
        }
        if (act) {
            ulonglong2 s0; s0.x = a0x; s0.y = a0y;
            *(ulonglong2*)&g_mg[(size_t)node * NCOL + ch * 4] = s0;
            if (node + G < N_) {
                ulonglong2 s1; s1.x = a1x; s1.y = a1y;
                *(ulonglong2*)&g_mg[(size_t)(node + G) * NCOL + ch * 4] = s1;
            }
        }
        h0 = p0; h1 = p1;
    }
}

// ---------------------------------------------------------------------------
// Group-0 layer-2 edge pass (forward edges, r in [0,20)):
// out[s,:] += v * mg[o][r][:]
__global__ void __launch_bounds__(256) k_l2e0(const int* __restrict__ src,
                                              const int* __restrict__ dst,
                                              const int* __restrict__ rel,
                                              float* __restrict__ out) {
    constexpr int NCOL = 20 * 16;
    int idx = blockIdx.x * 256 + threadIdx.x;
    if (idx >= E_ * 4) return;
    int q = idx & 3;
    int e = idx >> 2;
    int s = src[e], o = dst[e], r = rel[e];
    float v = 1.0f / (float)g_cnt[r * N_ + s];
    const float4 w = *(const float4*)&g_mg[(size_t)o * NCOL + r * 16 + q * 4];
    float* op = &out[s * C_ + q * 4];
    asm volatile("red.global.add.v4.f32 [%0], {%1, %2, %3, %4};"
                 :: "l"(op), "f"(v * w.x), "f"(v * w.y), "f"(v * w.z), "f"(v * w.w)
                 : "memory");
}

// Group-1 layer-2 edge pass (reverse edges r in [20,40) + self-loops r=40):
__global__ void __launch_bounds__(256) k_l2e1(const int* __restrict__ src,
                                              const int* __restrict__ dst,
                                              const int* __restrict__ rel,
                                              float* __restrict__ out) {
    constexpr int NCOL = 21 * 16;
    int idx = blockIdx.x * 256 + threadIdx.x;
    if (idx >= (E_ + N_) * 4) return;
    int q  = idx & 3;
    int e2 = idx >> 2;
    int s, o, rr;          // rr = local relation index within group (r - 20)
    float v;
    if (e2 < E_) {
        s = dst[e2]; o = src[e2]; rr = rel[e2];          // r = rel+20 -> rr = rel
        v = 1.0f / (float)g_cnt[(rr + R_) * N_ + s];
    } else {
        int n = e2 - E_;
        s = n; o = n; rr = 20; v = 1.0f;                 // r = 40 self-loop
    }
    const float4 w = *(const float4*)&g_mg[(size_t)o * NCOL + rr * 16 + q * 4];
    float* op = &out[s * C_ + q * 4];
    asm volatile("red.global.add.v4.f32 [%0], {%1, %2, %3, %4};"
                 :: "l"(op), "f"(v * w.x), "f"(v * w.y), "f"(v * w.z), "f"(v * w.w)
                 : "memory");
}

// ---------------------------------------------------------------------------
extern "C" void kernel_launch(void* const* d_in, const int* in_sizes, int n_in,
                              void* d_out, int out_size) {
    const int*   src    = (const int*)d_in[0];
    const int*   dst    = (const int*)d_in[1];
    const int*   rel    = (const int*)d_in[2];
    const float* comps1 = (const float*)d_in[3];
    const float* bases1 = (const float*)d_in[4];
    const float* comps2 = (const float*)d_in[5];
    const float* bases2 = (const float*)d_in[6];
    const float* bias1  = (const float*)d_in[7];
    const float* bias2  = (const float*)d_in[8];
    float* out = (float*)d_out;

    const int T = 256;
    k_pre            <<<(RT_ * N_ + T - 1) / T, T>>>(out, bias2, comps2, bases2);
    k_w1c            <<<WBn + CBn, T>>>(comps1, bases1, src, dst, rel);
    k_l1             <<<(2 * E_ * 4 + T - 1) / T, T>>>(src, dst, rel);
    k_mgemm_g<0, 20> <<<740, 128>>>(bias1);
    k_l2e0           <<<(E_ * 4 + T - 1) / T, T>>>(src, dst, rel, out);
    k_mgemm_g<20, 21><<<740, 128>>>(bias1);
    k_l2e1           <<<((E_ + N_) * 4 + T - 1) / T, T>>>(src, dst, rel, out);
}

// round 12
// speedup vs baseline: 1.1175x; 1.1175x over previous
#include <cuda_runtime.h>
#include <cuda_fp16.h>

// RGCN constants
constexpr int N_   = 50000;
constexpr int E_   = 500000;
constexpr int R_   = 20;
constexpr int RT_  = 41;            // 2R+1
constexpr int B_   = 40;
constexpr int EMB_ = 16;
constexpr int C_   = 16;
constexpr int NE_  = N_ * EMB_;     // 800000
constexpr int RC_  = RT_ * C_;      // 656
constexpr int CH_  = RC_ / 4;       // 164 float4-chunks
constexpr int JP_  = NE_ / 2;       // 400000 j-pairs
constexpr int WBn  = JP_ / 128;     // 3125 w1 blocks (256 thr, lane-pairs)
constexpr int CBn  = (E_ + 255) / 256;   // count blocks

// Scratch (static device globals) — big tensors stored fp16
__device__ __half g_w1h[(size_t)RT_ * NE_];  // [41][50000][16]  65.6 MB
__device__ float  g_h[NE_];                  // layer-1 pre-activations (fp32)
__device__ int    g_cnt[RT_ * N_];           // per-(r,s) edge counts
__device__ float  g_w2f[EMB_ * RC_];         // w2 flat [e][r*16+c]
__device__ __half g_mh[(size_t)N_ * RC_];    // m[o][r][c]  65.6 MB

// ---------------------------------------------------------------------------
// pre-pass: zero cnt & h, seed out with bias2, compute w2f. One launch.
__global__ void k_pre(float* __restrict__ out, const float* __restrict__ bias2,
                      const float* __restrict__ comps2,
                      const float* __restrict__ bases2) {
    int i = blockIdx.x * blockDim.x + threadIdx.x;
    if (i < RT_ * N_) g_cnt[i] = 0;
    if (i < NE_) { g_h[i] = 0.0f; out[i] = bias2[i & 15]; }
    if (i < RT_ * EMB_ * C_) {
        int r = i >> 8, ec = i & 255;
        int e = ec >> 4, c = ec & 15;
        float acc = 0.0f;
#pragma unroll
        for (int b = 0; b < B_; b++)
            acc = fmaf(comps2[r * B_ + b], bases2[b * 256 + ec], acc);
        g_w2f[e * RC_ + r * 16 + c] = acc;
    }
}

// ---------------------------------------------------------------------------
// Fused w1-GEMM + edge counting. Lane-pair b-split, f32x2, quad-packed comps.
// Result stored as fp16 (one half2 per j-pair per relation).
__global__ void __launch_bounds__(256) k_w1c(const float* __restrict__ comps1,
                                             const float* __restrict__ bases1,
                                             const int* __restrict__ src,
                                             const int* __restrict__ dst,
                                             const int* __restrict__ rel) {
    if (blockIdx.x >= WBn) {
        int i = (blockIdx.x - WBn) * 256 + threadIdx.x;
        if (i < E_) {
            int r = rel[i];
            atomicAdd(&g_cnt[r * N_ + src[i]], 1);
            atomicAdd(&g_cnt[(r + R_) * N_ + dst[i]], 1);
        }
        return;
    }

    __shared__ __align__(16) ulonglong2 cs4[RT_ * 20];
    for (int t = threadIdx.x; t < RT_ * 20; t += 256) {
        int r = t / 20, k = t % 20;
        unsigned int ca = __float_as_uint(comps1[r * B_ + 2 * k]);
        unsigned int cb = __float_as_uint(comps1[r * B_ + 2 * k + 1]);
        ulonglong2 q;
        asm("mov.b64 %0, {%1, %1};" : "=l"(q.x) : "r"(ca));
        asm("mov.b64 %0, {%1, %1};" : "=l"(q.y) : "r"(cb));
        cs4[t] = q;
    }
    __syncthreads();

    int half = threadIdx.x & 1;
    int jp   = blockIdx.x * 128 + (threadIdx.x >> 1);

    unsigned long long bp[20];                      // 20 x float2 = 40 regs
#pragma unroll
    for (int k = 0; k < 20; k++)
        bp[k] = *(const unsigned long long*)
                 &bases1[(size_t)(half * 20 + k) * NE_ + 2 * jp];

    int kbase = half * 10;
#pragma unroll 1
    for (int r = 0; r < RT_; r++) {
        const ulonglong2* cq = &cs4[r * 20 + kbase];
        unsigned long long acc = 0ull;
#pragma unroll
        for (int k = 0; k < 10; k++) {
            ulonglong2 q = cq[k];
            asm("fma.rn.f32x2 %0, %1, %2, %0;" : "+l"(acc) : "l"(bp[2*k]),   "l"(q.x));
            asm("fma.rn.f32x2 %0, %1, %2, %0;" : "+l"(acc) : "l"(bp[2*k+1]), "l"(q.y));
        }
        unsigned long long other = __shfl_xor_sync(0xffffffffu, acc, 1);
        asm("add.rn.f32x2 %0, %0, %1;" : "+l"(acc) : "l"(other));
        if (!half) {
            unsigned int lo, hi, h2;
            asm("mov.b64 {%0, %1}, %2;" : "=r"(lo), "=r"(hi) : "l"(acc));
            asm("cvt.rn.f16x2.f32 %0, %1, %2;" : "=r"(h2)
                : "f"(__uint_as_float(hi)), "f"(__uint_as_float(lo)));
            *(unsigned int*)&g_w1h[(size_t)r * NE_ + 2 * jp] = h2;
        }
    }
}

// ---------------------------------------------------------------------------
// layer-1 scatter: h[s,:] += v * w1[r, o, :].  4 lanes/edge; each loads
// 4 halves (8B) of w1, converts, one RED.v4 into fp32 h.
__global__ void k_l1(const int* __restrict__ src, const int* __restrict__ dst,
                     const int* __restrict__ rel) {
    int idx = blockIdx.x * blockDim.x + threadIdx.x;
    if (idx >= 2 * E_ * 4) return;
    int q  = idx & 3;
    int e2 = idx >> 2;
    int s, o, r;
    if (e2 < E_) { s = src[e2]; o = dst[e2]; r = rel[e2]; }
    else         { int e = e2 - E_; s = dst[e]; o = src[e]; r = rel[e] + R_; }
    float v = 1.0f / (float)g_cnt[r * N_ + s];
    const uint2 hw = *(const uint2*)&g_w1h[(size_t)r * NE_ + o * EMB_ + q * 4];
    float2 f01 = __half22float2(*(const __half2*)&hw.x);
    float2 f23 = __half22float2(*(const __half2*)&hw.y);
    float* hp = &g_h[s * EMB_ + q * 4];
    asm volatile("red.global.add.v4.f32 [%0], {%1, %2, %3, %4};"
                 :: "l"(hp), "f"(v * f01.x), "f"(v * f01.y),
                    "f"(v * f23.x), "f"(v * f23.y)
                 : "memory");
}

// ---------------------------------------------------------------------------
// m[o][rc] = sum_e relu(h[o,e]+w1[40,o,e]+bias1[e]) * w2f[e][rc]
// (relu epilogue fused). w2 in regs (packed f32x2); ILP-2 nodes; fp16 output.
__global__ void __launch_bounds__(192) k_mgemm(const float* __restrict__ bias1) {
    int w    = threadIdx.x >> 5;
    int lane = threadIdx.x & 31;
    int le   = lane & 15;
    int chunk = w * 32 + lane;
    bool act = chunk < CH_;
    int ch = act ? chunk : 0;

    ulonglong2 w2r[EMB_];                 // {w0,w1},{w2,w3} per e: 64 regs
#pragma unroll
    for (int e = 0; e < EMB_; e++)
        w2r[e] = *(const ulonglong2*)&g_w2f[e * RC_ + ch * 4];
    float breg = bias1[le];
    const __half* w1sl = &g_w1h[(size_t)(RT_ - 1) * NE_];

    const int G = gridDim.x;
    int node = blockIdx.x;
    float h0 = 0.0f, h1 = 0.0f;
    if (node < N_)
        h0 = fmaxf(g_h[node * EMB_ + le] + __half2float(w1sl[node * EMB_ + le]) + breg, 0.0f);
    if (node + G < N_)
        h1 = fmaxf(g_h[(node + G) * EMB_ + le] + __half2float(w1sl[(node + G) * EMB_ + le]) + breg, 0.0f);

    for (; node < N_; node += 2 * G) {
        int n2 = node + 2 * G, n3 = node + 3 * G;
        float p0 = 0.0f, p1 = 0.0f;
        if (n2 < N_)
            p0 = fmaxf(g_h[n2 * EMB_ + le] + __half2float(w1sl[n2 * EMB_ + le]) + breg, 0.0f);
        if (n3 < N_)
            p1 = fmaxf(g_h[n3 * EMB_ + le] + __half2float(w1sl[n3 * EMB_ + le]) + breg, 0.0f);

        unsigned long long a0x = 0ull, a0y = 0ull, a1x = 0ull, a1y = 0ull;
#pragma unroll
        for (int e = 0; e < EMB_; e++) {
            float he0 = __shfl_sync(0xffffffffu, h0, e);
            float he1 = __shfl_sync(0xffffffffu, h1, e);
            unsigned long long d0, d1;
            asm("mov.b64 %0, {%1, %1};" : "=l"(d0) : "r"(__float_as_uint(he0)));
            asm("mov.b64 %0, {%1, %1};" : "=l"(d1) : "r"(__float_as_uint(he1)));
            asm("fma.rn.f32x2 %0, %1, %2, %0;" : "+l"(a0x) : "l"(d0), "l"(w2r[e].x));
            asm("fma.rn.f32x2 %0, %1, %2, %0;" : "+l"(a0y) : "l"(d0), "l"(w2r[e].y));
            asm("fma.rn.f32x2 %0, %1, %2, %0;" : "+l"(a1x) : "l"(d1), "l"(w2r[e].x));
            asm("fma.rn.f32x2 %0, %1, %2, %0;" : "+l"(a1y) : "l"(d1), "l"(w2r[e].y));
        }
        if (act) {
            unsigned int lo, hi;
            uint2 st;
            asm("mov.b64 {%0, %1}, %2;" : "=r"(lo), "=r"(hi) : "l"(a0x));
            asm("cvt.rn.f16x2.f32 %0, %1, %2;" : "=r"(st.x)
                : "f"(__uint_as_float(hi)), "f"(__uint_as_float(lo)));
            asm("mov.b64 {%0, %1}, %2;" : "=r"(lo), "=r"(hi) : "l"(a0y));
            asm("cvt.rn.f16x2.f32 %0, %1, %2;" : "=r"(st.y)
                : "f"(__uint_as_float(hi)), "f"(__uint_as_float(lo)));
            *(uint2*)&g_mh[(size_t)node * RC_ + ch * 4] = st;
            if (node + G < N_) {
                asm("mov.b64 {%0, %1}, %2;" : "=r"(lo), "=r"(hi) : "l"(a1x));
                asm("cvt.rn.f16x2.f32 %0, %1, %2;" : "=r"(st.x)
                    : "f"(__uint_as_float(hi)), "f"(__uint_as_float(lo)));
                asm("mov.b64 {%0, %1}, %2;" : "=r"(lo), "=r"(hi) : "l"(a1y));
                asm("cvt.rn.f16x2.f32 %0, %1, %2;" : "=r"(st.y)
                    : "f"(__uint_as_float(hi)), "f"(__uint_as_float(lo)));
                *(uint2*)&g_mh[(size_t)(node + G) * RC_ + ch * 4] = st;
            }
        }
        h0 = p0; h1 = p1;
    }
}

// ---------------------------------------------------------------------------
// layer-2 edge pass incl. self-loop pseudo-edges: out[s,:] += v * m[o][r][:]
// fp16 gather (8B/lane), fp32 RED.
__global__ void k_l2e(const int* __restrict__ src, const int* __restrict__ dst,
                      const int* __restrict__ rel, float* __restrict__ out) {
    int idx = blockIdx.x * blockDim.x + threadIdx.x;
    if (idx >= (2 * E_ + N_) * 4) return;
    int q  = idx & 3;
    int e2 = idx >> 2;
    int s, o, r;
    float v;
    if (e2 < E_) {
        s = src[e2]; o = dst[e2]; r = rel[e2];
        v = 1.0f / (float)g_cnt[r * N_ + s];
    } else if (e2 < 2 * E_) {
        int e = e2 - E_;
        s = dst[e]; o = src[e]; r = rel[e] + R_;
        v = 1.0f / (float)g_cnt[r * N_ + s];
    } else {
        int n = e2 - 2 * E_;
        s = n; o = n; r = RT_ - 1; v = 1.0f;
    }
    const uint2 mw = *(const uint2*)&g_mh[(size_t)o * RC_ + r * 16 + q * 4];
    float2 f01 = __half22float2(*(const __half2*)&mw.x);
    float2 f23 = __half22float2(*(const __half2*)&mw.y);
    float* op = &out[s * C_ + q * 4];
    asm volatile("red.global.add.v4.f32 [%0], {%1, %2, %3, %4};"
                 :: "l"(op), "f"(v * f01.x), "f"(v * f01.y),
                    "f"(v * f23.x), "f"(v * f23.y)
                 : "memory");
}

// ---------------------------------------------------------------------------
extern "C" void kernel_launch(void* const* d_in, const int* in_sizes, int n_in,
                              void* d_out, int out_size) {
    const int*   src    = (const int*)d_in[0];
    const int*   dst    = (const int*)d_in[1];
    const int*   rel    = (const int*)d_in[2];
    const float* comps1 = (const float*)d_in[3];
    const float* bases1 = (const float*)d_in[4];
    const float* comps2 = (const float*)d_in[5];
    const float* bases2 = (const float*)d_in[6];
    const float* bias1  = (const float*)d_in[7];
    const float* bias2  = (const float*)d_in[8];
    float* out = (float*)d_out;

    const int T = 256;
    k_pre   <<<(RT_ * N_ + T - 1) / T, T>>>(out, bias2, comps2, bases2);
    k_w1c   <<<WBn + CBn, T>>>(comps1, bases1, src, dst, rel);
    k_l1    <<<(2 * E_ * 4 + T - 1) / T, T>>>(src, dst, rel);
    k_mgemm <<<444, 192>>>(bias1);
    k_l2e   <<<((2 * E_ + N_) * 4 + T - 1) / T, T>>>(src, dst, rel, out);
}

// round 13
// speedup vs baseline: 1.2154x; 1.0877x over previous
#include <cuda_runtime.h>
#include <cuda_fp16.h>

// RGCN constants
constexpr int N_   = 50000;
constexpr int E_   = 500000;
constexpr int R_   = 20;
constexpr int RT_  = 41;            // 2R+1
constexpr int B_   = 40;
constexpr int EMB_ = 16;
constexpr int C_   = 16;
constexpr int NE_  = N_ * EMB_;     // 800000
constexpr int RC_  = RT_ * C_;      // 656
constexpr int JP_  = NE_ / 2;       // 400000 j-pairs
constexpr int WBn  = JP_ / 128;     // 3125 w1 blocks (256 thr, lane-pairs)
constexpr int CBn  = (E_ + 255) / 256;   // count blocks
constexpr int NTILES_ = N_ / 16;    // 3125 node tiles (exact)
constexpr int CTILES_ = RC_ / 8;    // 82 col tiles (exact)
constexpr int NT_  = 4;             // node tiles staged per block in mgemm

// Scratch (static device globals) — big tensors stored fp16
__device__ __half g_w1h[(size_t)RT_ * NE_];  // [41][50000][16]  65.6 MB
__device__ float  g_h[NE_];                  // layer-1 edge-sum (fp32)
__device__ int    g_cnt[RT_ * N_];           // per-(r,s) edge counts
__device__ __half g_w2h[EMB_ * RC_];         // w2 flat [e][r*16+c], fp16
__device__ __half g_mh[(size_t)N_ * RC_];    // m[o][r][c]  65.6 MB

static __device__ __forceinline__ unsigned smem_u32(const void* p) {
    unsigned a;
    asm("{ .reg .u64 t; cvta.to.shared.u64 t, %1; cvt.u32.u64 %0, t; }"
        : "=r"(a) : "l"(p));
    return a;
}

// ---------------------------------------------------------------------------
// pre-pass: zero cnt & h, seed out with bias2, compute w2 (fp16). One launch.
__global__ void k_pre(float* __restrict__ out, const float* __restrict__ bias2,
                      const float* __restrict__ comps2,
                      const float* __restrict__ bases2) {
    int i = blockIdx.x * blockDim.x + threadIdx.x;
    if (i < RT_ * N_) g_cnt[i] = 0;
    if (i < NE_) { g_h[i] = 0.0f; out[i] = bias2[i & 15]; }
    if (i < RT_ * EMB_ * C_) {
        int r = i >> 8, ec = i & 255;
        int e = ec >> 4, c = ec & 15;
        float acc = 0.0f;
#pragma unroll
        for (int b = 0; b < B_; b++)
            acc = fmaf(comps2[r * B_ + b], bases2[b * 256 + ec], acc);
        g_w2h[e * RC_ + r * 16 + c] = __float2half_rn(acc);
    }
}

// ---------------------------------------------------------------------------
// Fused w1-GEMM + edge counting. Lane-pair b-split, f32x2, quad-packed comps.
// Result stored as fp16 (one half2 per j-pair per relation).
__global__ void __launch_bounds__(256) k_w1c(const float* __restrict__ comps1,
                                             const float* __restrict__ bases1,
                                             const int* __restrict__ src,
                                             const int* __restrict__ dst,
                                             const int* __restrict__ rel) {
    if (blockIdx.x >= WBn) {
        int i = (blockIdx.x - WBn) * 256 + threadIdx.x;
        if (i < E_) {
            int r = rel[i];
            atomicAdd(&g_cnt[r * N_ + src[i]], 1);
            atomicAdd(&g_cnt[(r + R_) * N_ + dst[i]], 1);
        }
        return;
    }

    __shared__ __align__(16) ulonglong2 cs4[RT_ * 20];
    for (int t = threadIdx.x; t < RT_ * 20; t += 256) {
        int r = t / 20, k = t % 20;
        unsigned int ca = __float_as_uint(comps1[r * B_ + 2 * k]);
        unsigned int cb = __float_as_uint(comps1[r * B_ + 2 * k + 1]);
        ulonglong2 q;
        asm("mov.b64 %0, {%1, %1};" : "=l"(q.x) : "r"(ca));
        asm("mov.b64 %0, {%1, %1};" : "=l"(q.y) : "r"(cb));
        cs4[t] = q;
    }
    __syncthreads();

    int half = threadIdx.x & 1;
    int jp   = blockIdx.x * 128 + (threadIdx.x >> 1);

    unsigned long long bp[20];                      // 20 x float2 = 40 regs
#pragma unroll
    for (int k = 0; k < 20; k++)
        bp[k] = *(const unsigned long long*)
                 &bases1[(size_t)(half * 20 + k) * NE_ + 2 * jp];

    int kbase = half * 10;
#pragma unroll 1
    for (int r = 0; r < RT_; r++) {
        const ulonglong2* cq = &cs4[r * 20 + kbase];
        unsigned long long acc = 0ull;
#pragma unroll
        for (int k = 0; k < 10; k++) {
            ulonglong2 q = cq[k];
            asm("fma.rn.f32x2 %0, %1, %2, %0;" : "+l"(acc) : "l"(bp[2*k]),   "l"(q.x));
            asm("fma.rn.f32x2 %0, %1, %2, %0;" : "+l"(acc) : "l"(bp[2*k+1]), "l"(q.y));
        }
        unsigned long long other = __shfl_xor_sync(0xffffffffu, acc, 1);
        asm("add.rn.f32x2 %0, %0, %1;" : "+l"(acc) : "l"(other));
        if (!half) {
            unsigned int lo, hi, h2;
            asm("mov.b64 {%0, %1}, %2;" : "=r"(lo), "=r"(hi) : "l"(acc));
            asm("cvt.rn.f16x2.f32 %0, %1, %2;" : "=r"(h2)
                : "f"(__uint_as_float(hi)), "f"(__uint_as_float(lo)));
            *(unsigned int*)&g_w1h[(size_t)r * NE_ + 2 * jp] = h2;
        }
    }
}

// ---------------------------------------------------------------------------
// layer-1 scatter: h[s,:] += v * w1[r, o, :].  4 lanes/edge, fp16 gather,
// one fp32 RED.v4.
__global__ void k_l1(const int* __restrict__ src, const int* __restrict__ dst,
                     const int* __restrict__ rel) {
    int idx = blockIdx.x * blockDim.x + threadIdx.x;
    if (idx >= 2 * E_ * 4) return;
    int q  = idx & 3;
    int e2 = idx >> 2;
    int s, o, r;
    if (e2 < E_) { s = src[e2]; o = dst[e2]; r = rel[e2]; }
    else         { int e = e2 - E_; s = dst[e]; o = src[e]; r = rel[e] + R_; }
    float v = 1.0f / (float)g_cnt[r * N_ + s];
    const uint2 hw = *(const uint2*)&g_w1h[(size_t)r * NE_ + o * EMB_ + q * 4];
    float2 f01 = __half22float2(*(const __half2*)&hw.x);
    float2 f23 = __half22float2(*(const __half2*)&hw.y);
    float* hp = &g_h[s * EMB_ + q * 4];
    asm volatile("red.global.add.v4.f32 [%0], {%1, %2, %3, %4};"
                 :: "l"(hp), "f"(v * f01.x), "f"(v * f01.y),
                    "f"(v * f23.x), "f"(v * f23.y)
                 : "memory");
}

// ---------------------------------------------------------------------------
// Tensor-core m-GEMM: m[n, rc] = sum_e relu(h[n,e]+w1[40,n,e]+b1[e]) * w2[e,rc]
// One mma.sync.m16n8k16 per (16-node, 8-col) tile; K=16 in one step.
// Block = 4 warps, stages NT_=4 node tiles (relu fused); warp w owns col
// tiles {w + 4t}. B-fragments live in registers for the whole kernel.
__global__ void __launch_bounds__(128) k_mgemm(const float* __restrict__ bias1) {
    __shared__ __half sA[NT_ * 256];     // [tile][row][e], 2KB
    int tid  = threadIdx.x;
    int lane = tid & 31;
    int w    = tid >> 5;

    // --- B fragments for this warp's col tiles ---
    int nOwn = (w < 2) ? 21 : 20;        // tiles w+4t, covers 0..81 exactly
    int k0   = (lane & 3) * 2;
    int nIdx = lane >> 2;
    unsigned bf0[21], bf1[21];
#pragma unroll
    for (int t = 0; t < 21; t++) {
        if (t < nOwn) {
            int n = (w + 4 * t) * 8 + nIdx;
            __half2 lo = __halves2half2(g_w2h[k0 * RC_ + n], g_w2h[(k0 + 1) * RC_ + n]);
            __half2 hi = __halves2half2(g_w2h[(k0 + 8) * RC_ + n], g_w2h[(k0 + 9) * RC_ + n]);
            bf0[t] = *(unsigned*)&lo;
            bf1[t] = *(unsigned*)&hi;
        }
    }

    // --- stage NT_ node tiles of relu'd h as fp16 ---
    int tile0 = blockIdx.x * NT_;
    const __half* w1sl = &g_w1h[(size_t)(RT_ - 1) * NE_];
    for (int i = tid; i < NT_ * 256; i += 128) {
        int node = tile0 * 16 + (i >> 4);
        int e = i & 15;
        float x = 0.0f;
        if (node < N_)
            x = fmaxf(g_h[node * EMB_ + e] + __half2float(w1sl[node * EMB_ + e])
                      + bias1[e], 0.0f);
        sA[i] = __float2half_rn(x);
    }
    __syncthreads();

    unsigned abase = smem_u32(sA) + (lane & 15) * 32 + (lane >> 4) * 16;
    int rowq = lane >> 2;                // output row within tile
    int colq = (lane & 3) * 2;           // output col pair within 8-col tile

#pragma unroll 1
    for (int tt = 0; tt < NT_; tt++) {
        int gt = tile0 + tt;
        if (gt >= NTILES_) break;
        unsigned a0, a1, a2, a3;
        asm("ldmatrix.sync.aligned.m8n8.x4.shared.b16 {%0,%1,%2,%3}, [%4];"
            : "=r"(a0), "=r"(a1), "=r"(a2), "=r"(a3)
            : "r"(abase + tt * 512));
        size_t rowbase = (size_t)(gt * 16 + rowq) * RC_;
#pragma unroll
        for (int t = 0; t < 21; t++) {
            if (t >= nOwn) break;
            float d0, d1, d2, d3;
            asm("mma.sync.aligned.m16n8k16.row.col.f32.f16.f16.f32 "
                "{%0,%1,%2,%3}, {%4,%5,%6,%7}, {%8,%9}, {%10,%11,%12,%13};"
                : "=f"(d0), "=f"(d1), "=f"(d2), "=f"(d3)
                : "r"(a0), "r"(a1), "r"(a2), "r"(a3), "r"(bf0[t]), "r"(bf1[t]),
                  "f"(0.0f), "f"(0.0f), "f"(0.0f), "f"(0.0f));
            unsigned s0, s1;
            asm("cvt.rn.f16x2.f32 %0, %1, %2;" : "=r"(s0) : "f"(d1), "f"(d0));
            asm("cvt.rn.f16x2.f32 %0, %1, %2;" : "=r"(s1) : "f"(d3), "f"(d2));
            int col = (w + 4 * t) * 8 + colq;
            *(unsigned*)&g_mh[rowbase + col] = s0;
            *(unsigned*)&g_mh[rowbase + (size_t)8 * RC_ + col] = s1;
        }
    }
}

// ---------------------------------------------------------------------------
// layer-2 edge pass incl. self-loop pseudo-edges: out[s,:] += v * m[o][r][:]
__global__ void k_l2e(const int* __restrict__ src, const int* __restrict__ dst,
                      const int* __restrict__ rel, float* __restrict__ out) {
    int idx = blockIdx.x * blockDim.x + threadIdx.x;
    if (idx >= (2 * E_ + N_) * 4) return;
    int q  = idx & 3;
    int e2 = idx >> 2;
    int s, o, r;
    float v;
    if (e2 < E_) {
        s = src[e2]; o = dst[e2]; r = rel[e2];
        v = 1.0f / (float)g_cnt[r * N_ + s];
    } else if (e2 < 2 * E_) {
        int e = e2 - E_;
        s = dst[e]; o = src[e]; r = rel[e] + R_;
        v = 1.0f / (float)g_cnt[r * N_ + s];
    } else {
        int n = e2 - 2 * E_;
        s = n; o = n; r = RT_ - 1; v = 1.0f;
    }
    const uint2 mw = *(const uint2*)&g_mh[(size_t)o * RC_ + r * 16 + q * 4];
    float2 f01 = __half22float2(*(const __half2*)&mw.x);
    float2 f23 = __half22float2(*(const __half2*)&mw.y);
    float* op = &out[s * C_ + q * 4];
    asm volatile("red.global.add.v4.f32 [%0], {%1, %2, %3, %4};"
                 :: "l"(op), "f"(v * f01.x), "f"(v * f01.y),
                    "f"(v * f23.x), "f"(v * f23.y)
                 : "memory");
}

// ---------------------------------------------------------------------------
extern "C" void kernel_launch(void* const* d_in, const int* in_sizes, int n_in,
                              void* d_out, int out_size) {
    const int*   src    = (const int*)d_in[0];
    const int*   dst    = (const int*)d_in[1];
    const int*   rel    = (const int*)d_in[2];
    const float* comps1 = (const float*)d_in[3];
    const float* bases1 = (const float*)d_in[4];
    const float* comps2 = (const float*)d_in[5];
    const float* bases2 = (const float*)d_in[6];
    const float* bias1  = (const float*)d_in[7];
    const float* bias2  = (const float*)d_in[8];
    float* out = (float*)d_out;

    const int T = 256;
    k_pre   <<<(RT_ * N_ + T - 1) / T, T>>>(out, bias2, comps2, bases2);
    k_w1c   <<<WBn + CBn, T>>>(comps1, bases1, src, dst, rel);
    k_l1    <<<(2 * E_ * 4 + T - 1) / T, T>>>(src, dst, rel);
    k_mgemm <<<(NTILES_ + NT_ - 1) / NT_, 128>>>(bias1);
    k_l2e   <<<((2 * E_ + N_) * 4 + T - 1) / T, T>>>(src, dst, rel, out);
}

// round 14
// speedup vs baseline: 1.3253x; 1.0904x over previous
#include <cuda_runtime.h>
#include <cuda_fp16.h>

// RGCN constants
constexpr int N_   = 50000;
constexpr int E_   = 500000;
constexpr int R_   = 20;
constexpr int RT_  = 41;            // 2R+1
constexpr int B_   = 40;
constexpr int EMB_ = 16;
constexpr int C_   = 16;
constexpr int NE_  = N_ * EMB_;     // 800000
constexpr int RC_  = RT_ * C_;      // 656
constexpr int JP_  = NE_ / 2;       // 400000 j-pairs
constexpr int WBn  = JP_ / 128;     // 3125 w1 blocks (256 thr, lane-pairs)
constexpr int CBn  = (E_ + 255) / 256;   // count blocks
constexpr int NTILES_ = N_ / 16;    // 3125 node tiles (exact)
constexpr int NT_  = 4;             // node tiles per block in mgemm

// Scratch (static device globals) — big tensors stored fp16
__device__ __half g_w1h[(size_t)RT_ * NE_];  // [41][50000][16]  65.6 MB
__device__ float  g_h[NE_];                  // layer-1 edge-sum (fp32)
__device__ int    g_cnt[RT_ * N_];           // per-(r,s) edge counts
__device__ __half g_w2h[EMB_ * RC_];         // w2 flat [e][r*16+c], fp16
__device__ __half g_mh[(size_t)N_ * RC_];    // m[o][r][c]  65.6 MB

static __device__ __forceinline__ unsigned smem_u32(const void* p) {
    unsigned a;
    asm("{ .reg .u64 t; cvta.to.shared.u64 t, %1; cvt.u32.u64 %0, t; }"
        : "=r"(a) : "l"(p));
    return a;
}

// ---------------------------------------------------------------------------
// pre-pass: zero cnt & h, seed out with bias2, compute w2 (fp16). One launch.
__global__ void k_pre(float* __restrict__ out, const float* __restrict__ bias2,
                      const float* __restrict__ comps2,
                      const float* __restrict__ bases2) {
    int i = blockIdx.x * blockDim.x + threadIdx.x;
    if (i < RT_ * N_) g_cnt[i] = 0;
    if (i < NE_) { g_h[i] = 0.0f; out[i] = bias2[i & 15]; }
    if (i < RT_ * EMB_ * C_) {
        int r = i >> 8, ec = i & 255;
        int e = ec >> 4, c = ec & 15;
        float acc = 0.0f;
#pragma unroll
        for (int b = 0; b < B_; b++)
            acc = fmaf(comps2[r * B_ + b], bases2[b * 256 + ec], acc);
        g_w2h[e * RC_ + r * 16 + c] = __float2half_rn(acc);
    }
}

// ---------------------------------------------------------------------------
// Fused w1-GEMM + edge counting. Lane-pair b-split, f32x2, quad-packed comps.
__global__ void __launch_bounds__(256) k_w1c(const float* __restrict__ comps1,
                                             const float* __restrict__ bases1,
                                             const int* __restrict__ src,
                                             const int* __restrict__ dst,
                                             const int* __restrict__ rel) {
    if (blockIdx.x >= WBn) {
        int i = (blockIdx.x - WBn) * 256 + threadIdx.x;
        if (i < E_) {
            int r = rel[i];
            atomicAdd(&g_cnt[r * N_ + src[i]], 1);
            atomicAdd(&g_cnt[(r + R_) * N_ + dst[i]], 1);
        }
        return;
    }

    __shared__ __align__(16) ulonglong2 cs4[RT_ * 20];
    for (int t = threadIdx.x; t < RT_ * 20; t += 256) {
        int r = t / 20, k = t % 20;
        unsigned int ca = __float_as_uint(comps1[r * B_ + 2 * k]);
        unsigned int cb = __float_as_uint(comps1[r * B_ + 2 * k + 1]);
        ulonglong2 q;
        asm("mov.b64 %0, {%1, %1};" : "=l"(q.x) : "r"(ca));
        asm("mov.b64 %0, {%1, %1};" : "=l"(q.y) : "r"(cb));
        cs4[t] = q;
    }
    __syncthreads();

    int half = threadIdx.x & 1;
    int jp   = blockIdx.x * 128 + (threadIdx.x >> 1);

    unsigned long long bp[20];                      // 20 x float2 = 40 regs
#pragma unroll
    for (int k = 0; k < 20; k++)
        bp[k] = *(const unsigned long long*)
                 &bases1[(size_t)(half * 20 + k) * NE_ + 2 * jp];

    int kbase = half * 10;
#pragma unroll 1
    for (int r = 0; r < RT_; r++) {
        const ulonglong2* cq = &cs4[r * 20 + kbase];
        unsigned long long acc = 0ull;
#pragma unroll
        for (int k = 0; k < 10; k++) {
            ulonglong2 q = cq[k];
            asm("fma.rn.f32x2 %0, %1, %2, %0;" : "+l"(acc) : "l"(bp[2*k]),   "l"(q.x));
            asm("fma.rn.f32x2 %0, %1, %2, %0;" : "+l"(acc) : "l"(bp[2*k+1]), "l"(q.y));
        }
        unsigned long long other = __shfl_xor_sync(0xffffffffu, acc, 1);
        asm("add.rn.f32x2 %0, %0, %1;" : "+l"(acc) : "l"(other));
        if (!half) {
            unsigned int lo, hi, h2;
            asm("mov.b64 {%0, %1}, %2;" : "=r"(lo), "=r"(hi) : "l"(acc));
            asm("cvt.rn.f16x2.f32 %0, %1, %2;" : "=r"(h2)
                : "f"(__uint_as_float(hi)), "f"(__uint_as_float(lo)));
            *(unsigned int*)&g_w1h[(size_t)r * NE_ + 2 * jp] = h2;
        }
    }
}

// ---------------------------------------------------------------------------
// layer-1 scatter: h[s,:] += v * w1[r, o, :].  4 lanes/edge, fp16 gather,
// one fp32 RED.v4.
__global__ void k_l1(const int* __restrict__ src, const int* __restrict__ dst,
                     const int* __restrict__ rel) {
    int idx = blockIdx.x * blockDim.x + threadIdx.x;
    if (idx >= 2 * E_ * 4) return;
    int q  = idx & 3;
    int e2 = idx >> 2;
    int s, o, r;
    if (e2 < E_) { s = src[e2]; o = dst[e2]; r = rel[e2]; }
    else         { int e = e2 - E_; s = dst[e]; o = src[e]; r = rel[e] + R_; }
    float v = 1.0f / (float)g_cnt[r * N_ + s];
    const uint2 hw = *(const uint2*)&g_w1h[(size_t)r * NE_ + o * EMB_ + q * 4];
    float2 f01 = __half22float2(*(const __half2*)&hw.x);
    float2 f23 = __half22float2(*(const __half2*)&hw.y);
    float* hp = &g_h[s * EMB_ + q * 4];
    asm volatile("red.global.add.v4.f32 [%0], {%1, %2, %3, %4};"
                 :: "l"(hp), "f"(v * f01.x), "f"(v * f01.y),
                    "f"(v * f23.x), "f"(v * f23.y)
                 : "memory");
}

// ---------------------------------------------------------------------------
// Tensor-core m-GEMM with smem-staged epilogue.
// m[n, rc] = sum_e relu(h[n,e]+w1[40,n,e]+b1[e]) * w2[e,rc]
// Per node tile: ldmatrix A, 20-21 mma per warp into sOut via STS.32, then a
// flat coalesced 21KB copy sOut -> g_mh (the tile's rows are contiguous).
__global__ void __launch_bounds__(128) k_mgemm(const float* __restrict__ bias1) {
    __shared__ __half sA[256];             // one node tile [16][16]
    __shared__ __align__(16) __half sOut[16 * RC_];  // 21 KB
    int tid  = threadIdx.x;
    int lane = tid & 31;
    int w    = tid >> 5;

    // --- B fragments for this warp's col tiles {w + 4t} ---
    int nOwn = (w < 2) ? 21 : 20;
    int k0   = (lane & 3) * 2;
    int nIdx = lane >> 2;
    unsigned bf0[21], bf1[21];
#pragma unroll
    for (int t = 0; t < 21; t++) {
        if (t < nOwn) {
            int n = (w + 4 * t) * 8 + nIdx;
            __half2 lo = __halves2half2(g_w2h[k0 * RC_ + n], g_w2h[(k0 + 1) * RC_ + n]);
            __half2 hi = __halves2half2(g_w2h[(k0 + 8) * RC_ + n], g_w2h[(k0 + 9) * RC_ + n]);
            bf0[t] = *(unsigned*)&lo;
            bf1[t] = *(unsigned*)&hi;
        }
    }

    const __half* w1sl = &g_w1h[(size_t)(RT_ - 1) * NE_];
    unsigned abase = smem_u32(sA) + (lane & 15) * 32 + (lane >> 4) * 16;
    int rowq = lane >> 2;
    int colq = (lane & 3) * 2;

    int tile0 = blockIdx.x * NT_;
#pragma unroll 1
    for (int tt = 0; tt < NT_; tt++) {
        int gt = tile0 + tt;
        if (gt >= NTILES_) break;

        // stage relu'd h tile (2 elems per thread)
        for (int i = tid; i < 256; i += 128) {
            int node = gt * 16 + (i >> 4);
            int e = i & 15;
            float x = fmaxf(g_h[node * EMB_ + e]
                            + __half2float(w1sl[node * EMB_ + e]) + bias1[e], 0.0f);
            sA[i] = __float2half_rn(x);
        }
        __syncthreads();

        unsigned a0, a1, a2, a3;
        asm("ldmatrix.sync.aligned.m8n8.x4.shared.b16 {%0,%1,%2,%3}, [%4];"
            : "=r"(a0), "=r"(a1), "=r"(a2), "=r"(a3) : "r"(abase));
#pragma unroll
        for (int t = 0; t < 21; t++) {
            if (t >= nOwn) break;
            float d0, d1, d2, d3;
            asm("mma.sync.aligned.m16n8k16.row.col.f32.f16.f16.f32 "
                "{%0,%1,%2,%3}, {%4,%5,%6,%7}, {%8,%9}, {%10,%11,%12,%13};"
                : "=f"(d0), "=f"(d1), "=f"(d2), "=f"(d3)
                : "r"(a0), "r"(a1), "r"(a2), "r"(a3), "r"(bf0[t]), "r"(bf1[t]),
                  "f"(0.0f), "f"(0.0f), "f"(0.0f), "f"(0.0f));
            unsigned s0, s1;
            asm("cvt.rn.f16x2.f32 %0, %1, %2;" : "=r"(s0) : "f"(d1), "f"(d0));
            asm("cvt.rn.f16x2.f32 %0, %1, %2;" : "=r"(s1) : "f"(d3), "f"(d2));
            int col = (w + 4 * t) * 8 + colq;
            *(unsigned*)&sOut[rowq * RC_ + col] = s0;
            *(unsigned*)&sOut[(rowq + 8) * RC_ + col] = s1;
        }
        __syncthreads();

        // flat coalesced copy: 16*656 halves = 2624 uint4, contiguous in g_mh
        uint4* dst4 = (uint4*)&g_mh[(size_t)gt * 16 * RC_];
        const uint4* src4 = (const uint4*)sOut;
        for (int i = tid; i < 16 * RC_ / 8; i += 128)
            dst4[i] = src4[i];
        __syncthreads();
    }
}

// ---------------------------------------------------------------------------
// layer-2 edge pass incl. self-loop pseudo-edges: out[s,:] += v * m[o][r][:]
__global__ void k_l2e(const int* __restrict__ src, const int* __restrict__ dst,
                      const int* __restrict__ rel, float* __restrict__ out) {
    int idx = blockIdx.x * blockDim.x + threadIdx.x;
    if (idx >= (2 * E_ + N_) * 4) return;
    int q  = idx & 3;
    int e2 = idx >> 2;
    int s, o, r;
    float v;
    if (e2 < E_) {
        s = src[e2]; o = dst[e2]; r = rel[e2];
        v = 1.0f / (float)g_cnt[r * N_ + s];
    } else if (e2 < 2 * E_) {
        int e = e2 - E_;
        s = dst[e]; o = src[e]; r = rel[e] + R_;
        v = 1.0f / (float)g_cnt[r * N_ + s];
    } else {
        int n = e2 - 2 * E_;
        s = n; o = n; r = RT_ - 1; v = 1.0f;
    }
    const uint2 mw = *(const uint2*)&g_mh[(size_t)o * RC_ + r * 16 + q * 4];
    float2 f01 = __half22float2(*(const __half2*)&mw.x);
    float2 f23 = __half22float2(*(const __half2*)&mw.y);
    float* op = &out[s * C_ + q * 4];
    asm volatile("red.global.add.v4.f32 [%0], {%1, %2, %3, %4};"
                 :: "l"(op), "f"(v * f01.x), "f"(v * f01.y),
                    "f"(v * f23.x), "f"(v * f23.y)
                 : "memory");
}

// ---------------------------------------------------------------------------
extern "C" void kernel_launch(void* const* d_in, const int* in_sizes, int n_in,
                              void* d_out, int out_size) {
    const int*   src    = (const int*)d_in[0];
    const int*   dst    = (const int*)d_in[1];
    const int*   rel    = (const int*)d_in[2];
    const float* comps1 = (const float*)d_in[3];
    const float* bases1 = (const float*)d_in[4];
    const float* comps2 = (const float*)d_in[5];
    const float* bases2 = (const float*)d_in[6];
    const float* bias1  = (const float*)d_in[7];
    const float* bias2  = (const float*)d_in[8];
    float* out = (float*)d_out;

    const int T = 256;
    k_pre   <<<(RT_ * N_ + T - 1) / T, T>>>(out, bias2, comps2, bases2);
    k_w1c   <<<WBn + CBn, T>>>(comps1, bases1, src, dst, rel);
    k_l1    <<<(2 * E_ * 4 + T - 1) / T, T>>>(src, dst, rel);
    k_mgemm <<<(NTILES_ + NT_ - 1) / NT_, 128>>>(bias1);
    k_l2e   <<<((2 * E_ + N_) * 4 + T - 1) / T, T>>>(src, dst, rel, out);
}